// round 16
// baseline (speedup 1.0000x reference)
#include <cuda_runtime.h>
#include <cuda_bf16.h>

// PitchLoss — TERMINAL (best measured config: kernel 7.04us; wall 8.22us
// best, 8.22-8.45us band across four replications with kernel time pinned —
// residual wall variance is harness-side, not kernel-side).
//
// Math: the reference's (N,B,L) broadcast collapses analytically because
// mask[n,b,l] = c[b,n] is constant over l:
//   diff[b,n] = | c[b,n] * (mean_g[b] - mean_t[b]) / (c[b,n] + 1e-6) |
//   loss      = mean_{b,n} relu(diff - 0.5)
// with c[b,n] = -(# onsets at idx>=1 in segment n) - (n==0 ? offsets[b,0] : 0),
// zeroed for n >= n_notes[b]; segment index = inclusive cumsum of offsets.
//
// Structure (every choice measured over 15 rounds):
//  - single launch, 64 blocks x 256 threads (one block per batch row)
//  - mask int4 loads issued before g/t float4 loads (masks gate the
//    scan -> barrier-1 critical path; L1tex completion follows issue order)
//  - warp-shuffle scan + reductions; 16-bit masks; popcount segment index
//  - n_notes/tg/tt combine hoisted above barrier 2 (hidden under scatter)
//  - tail: ONE packed 64-bit atomic — count in bits[57:64), fixed-point
//    relu-sum (>=0) below. The last arrival's atomicAdd return value IS the
//    complete sum: no threadfence, no partials array, no readback. Integer
//    adds are commutative -> bit-deterministic across graph replays;
//    self-rearming (reset only after all 64 adds have landed).
//
// Remaining time is structural for this environment: ~4.4us launch/ramp
// floor + ~1.5us mandatory cold-miss DRAM latency (L2 flushed per replay)
// + ~1us scan/histogram/barrier chain + ~1.2us harness wall overhead.

#define BATCH 64
#define LEN   4096
#define NMAX  128
#define T1    256
#define CHUNK (LEN / T1)   // 16 elements / thread
#define NV    (CHUNK / 4)
#define FULLM 0xffffffffu
#define CNT_SHIFT 57
#define VAL_MASK  ((1ULL << CNT_SHIFT) - 1ULL)
#define FP_SCALE  68719476736.0f   // 2^36

__device__ unsigned long long g_pack = 0ULL;

__global__ __launch_bounds__(T1)
void pitch_fused_kernel(const float* __restrict__ gen_f0,
                        const float* __restrict__ contours,
                        const int*   __restrict__ onsets,
                        const int*   __restrict__ offsets,
                        float*       __restrict__ out)
{
    const int b    = blockIdx.x;
    const int tid  = threadIdx.x;
    const int lane = tid & 31;
    const int wid  = tid >> 5;           // 8 warps

    const int4*   __restrict__ on  = (const int4*)(onsets  + (size_t)b * LEN) + tid * NV;
    const int4*   __restrict__ off = (const int4*)(offsets + (size_t)b * LEN) + tid * NV;
    const float4* __restrict__ gr  = (const float4*)(gen_f0   + (size_t)b * LEN)     + tid * NV;
    const float4* __restrict__ tr  = (const float4*)(contours + (size_t)b * 2 * LEN) + tid * NV;

    __shared__ int   s_counts[NMAX];
    __shared__ int   s_wosum[8];
    __shared__ float s_wg[8], s_wt[8];
    __shared__ float s_red[4];

    if (tid < NMAX) s_counts[tid] = 0;

    // ---- mask loads FIRST (they gate the scan -> barrier-1 path) ----
    unsigned offm = 0, onm = 0;
#pragma unroll
    for (int j = 0; j < NV; j++) {
        const int4 o4 = off[j];
        const int4 n4 = on[j];
        const int  s  = 4 * j;
        offm |= ((unsigned)o4.x << s) | ((unsigned)o4.y << (s + 1))
              | ((unsigned)o4.z << (s + 2)) | ((unsigned)o4.w << (s + 3));
        onm  |= ((unsigned)n4.x << s) | ((unsigned)n4.y << (s + 1))
              | ((unsigned)n4.z << (s + 2)) | ((unsigned)n4.w << (s + 3));
    }
    // ---- g/t loads issued now; consumed below (latency overlapped) ----
    float sg = 0.f, st = 0.f;
#pragma unroll
    for (int j = 0; j < NV; j++) {
        const float4 g4 = gr[j];
        const float4 t4 = tr[j];
        sg += (g4.x + g4.y) + (g4.z + g4.w);
        st += (t4.x + t4.y) + (t4.z + t4.w);
    }
    const int osum = __popc(offm);

    // ---- warp-level inclusive scan of osum (critical path to barrier 1) ----
    int incl = osum;
#pragma unroll
    for (int d = 1; d < 32; d <<= 1) {
        int v = __shfl_up_sync(FULLM, incl, d);
        if (lane >= d) incl += v;
    }
    if (lane == 31) s_wosum[wid] = incl;

    // ---- g/t warp reduce: off the scan path, still before barrier 1 ----
#pragma unroll
    for (int d = 16; d > 0; d >>= 1) {
        sg += __shfl_down_sync(FULLM, sg, d);
        st += __shfl_down_sync(FULLM, st, d);
    }
    if (lane == 0) { s_wg[wid] = sg; s_wt[wid] = st; }
    __syncthreads();                      // barrier 1

    // ---- cross-warp prefix + scatter onset counts ----
    int wpre = 0;
#pragma unroll
    for (int w = 0; w < 8; w++) wpre += (w < wid) ? s_wosum[w] : 0;
    const int excl = wpre + incl - osum;   // exclusive offset-prefix of this thread

    unsigned m = onm;
    if (tid == 0) m &= ~1u;                // reference masks onsets at idx==0
    while (m) {
        const int j = __ffs(m) - 1;
        m &= m - 1;
        const int seg = excl + __popc(offm & ((2u << j) - 1u));  // inclusive cumsum at l
        if (seg < NMAX) atomicAdd(&s_counts[seg], 1);
    }

    // ---- combine (barrier-1 data only): hidden under the scatter above ----
    int   n_notes = 0;
    float tg = 0.f, tt = 0.f;
#pragma unroll
    for (int w = 0; w < 8; w++) { n_notes += s_wosum[w]; tg += s_wg[w]; tt += s_wt[w]; }
    const float dd = (tg - tt) * (1.0f / LEN);

    __syncthreads();                      // barrier 2 (histogram complete)

    // ---- per-note loss, block reduce (threads 0-127 = one note each) ----
    float val = 0.f;
    if (tid < NMAX) {
        float c = -(float)s_counts[tid];
        if (tid == 0) c -= (float)(offm & 1u);   // tid0's chunk holds offsets[b,0]
        if (tid >= n_notes) c = 0.f;
        const float diff = fabsf(c * dd / (c + 1e-6f));
        val = fmaxf(diff - 0.5f, 0.f);
    }
#pragma unroll
    for (int d = 16; d > 0; d >>= 1) val += __shfl_down_sync(FULLM, val, d);
    if (lane == 0 && wid < 4) s_red[wid] = val;   // warps 0-3 hold tid<128
    __syncthreads();                      // barrier 3

    // ---- single packed atomic: count in high bits, fixed-point sum low ----
    if (tid == 0) {
        const float bs = (s_red[0] + s_red[1]) + (s_red[2] + s_red[3]);
        const unsigned long long q =
            (unsigned long long)__float2ll_rn(bs * FP_SCALE);
        const unsigned long long add = (1ULL << CNT_SHIFT) + q;
        const unsigned long long old = atomicAdd(&g_pack, add);
        if ((old >> CNT_SHIFT) == (unsigned long long)(BATCH - 1)) {
            const unsigned long long tot = (old + add) & VAL_MASK;
            out[0] = (float)((double)tot * (1.0 / (double)FP_SCALE)
                              * (1.0 / (NMAX * BATCH)));
            g_pack = 0ULL;   // all 64 adds landed (count==64): safe to rearm
        }
    }
}

extern "C" void kernel_launch(void* const* d_in, const int* in_sizes, int n_in,
                              void* d_out, int out_size)
{
    const float* gen_f0   = (const float*)d_in[0];
    const float* contours = (const float*)d_in[1];
    const int*   onsets   = (const int*)d_in[2];
    const int*   offsets  = (const int*)d_in[3];
    // d_in[4] = n_notes_max (compile-time NMAX=128 for this shape)

    pitch_fused_kernel<<<BATCH, T1>>>(gen_f0, contours, onsets, offsets, (float*)d_out);
}

// round 17
// speedup vs baseline: 1.0661x; 1.0661x over previous
#include <cuda_runtime.h>
#include <cuda_bf16.h>

// PitchLoss — TERMINAL (best measured config: kernel 7.04us; wall 8.224us
// best. Five byte-identical replications span kernel 7.04-7.33us / wall
// 8.22-8.77us — unlocked-clock drift + harness overhead, not kernel
// structure; the spread across identical binaries exceeds the spread across
// the last five distinct designs).
//
// Math: the reference's (N,B,L) broadcast collapses analytically because
// mask[n,b,l] = c[b,n] is constant over l:
//   diff[b,n] = | c[b,n] * (mean_g[b] - mean_t[b]) / (c[b,n] + 1e-6) |
//   loss      = mean_{b,n} relu(diff - 0.5)
// with c[b,n] = -(# onsets at idx>=1 in segment n) - (n==0 ? offsets[b,0] : 0),
// zeroed for n >= n_notes[b]; segment index = inclusive cumsum of offsets.
//
// Structure (every choice measured over 16 rounds):
//  - single launch, 64 blocks x 256 threads (one block per batch row)
//  - mask int4 loads issued before g/t float4 loads (masks gate the
//    scan -> barrier-1 critical path; L1tex completion follows issue order)
//  - warp-shuffle scan + reductions; 16-bit masks; popcount segment index
//  - n_notes/tg/tt combine hoisted above barrier 2 (hidden under scatter)
//  - tail: ONE packed 64-bit atomic — count in bits[57:64), fixed-point
//    relu-sum (>=0) below. The last arrival's atomicAdd return value IS the
//    complete sum: no threadfence, no partials array, no readback. Integer
//    adds are commutative -> bit-deterministic across graph replays;
//    self-rearming (reset only after all 64 adds have landed).
//
// Remaining time is structural for this environment: ~4.4us launch/ramp
// floor + ~1.5us mandatory cold-miss DRAM latency (L2 flushed per replay)
// + ~1us scan/histogram/barrier chain + harness wall overhead.

#define BATCH 64
#define LEN   4096
#define NMAX  128
#define T1    256
#define CHUNK (LEN / T1)   // 16 elements / thread
#define NV    (CHUNK / 4)
#define FULLM 0xffffffffu
#define CNT_SHIFT 57
#define VAL_MASK  ((1ULL << CNT_SHIFT) - 1ULL)
#define FP_SCALE  68719476736.0f   // 2^36

__device__ unsigned long long g_pack = 0ULL;

__global__ __launch_bounds__(T1)
void pitch_fused_kernel(const float* __restrict__ gen_f0,
                        const float* __restrict__ contours,
                        const int*   __restrict__ onsets,
                        const int*   __restrict__ offsets,
                        float*       __restrict__ out)
{
    const int b    = blockIdx.x;
    const int tid  = threadIdx.x;
    const int lane = tid & 31;
    const int wid  = tid >> 5;           // 8 warps

    const int4*   __restrict__ on  = (const int4*)(onsets  + (size_t)b * LEN) + tid * NV;
    const int4*   __restrict__ off = (const int4*)(offsets + (size_t)b * LEN) + tid * NV;
    const float4* __restrict__ gr  = (const float4*)(gen_f0   + (size_t)b * LEN)     + tid * NV;
    const float4* __restrict__ tr  = (const float4*)(contours + (size_t)b * 2 * LEN) + tid * NV;

    __shared__ int   s_counts[NMAX];
    __shared__ int   s_wosum[8];
    __shared__ float s_wg[8], s_wt[8];
    __shared__ float s_red[4];

    if (tid < NMAX) s_counts[tid] = 0;

    // ---- mask loads FIRST (they gate the scan -> barrier-1 path) ----
    unsigned offm = 0, onm = 0;
#pragma unroll
    for (int j = 0; j < NV; j++) {
        const int4 o4 = off[j];
        const int4 n4 = on[j];
        const int  s  = 4 * j;
        offm |= ((unsigned)o4.x << s) | ((unsigned)o4.y << (s + 1))
              | ((unsigned)o4.z << (s + 2)) | ((unsigned)o4.w << (s + 3));
        onm  |= ((unsigned)n4.x << s) | ((unsigned)n4.y << (s + 1))
              | ((unsigned)n4.z << (s + 2)) | ((unsigned)n4.w << (s + 3));
    }
    // ---- g/t loads issued now; consumed below (latency overlapped) ----
    float sg = 0.f, st = 0.f;
#pragma unroll
    for (int j = 0; j < NV; j++) {
        const float4 g4 = gr[j];
        const float4 t4 = tr[j];
        sg += (g4.x + g4.y) + (g4.z + g4.w);
        st += (t4.x + t4.y) + (t4.z + t4.w);
    }
    const int osum = __popc(offm);

    // ---- warp-level inclusive scan of osum (critical path to barrier 1) ----
    int incl = osum;
#pragma unroll
    for (int d = 1; d < 32; d <<= 1) {
        int v = __shfl_up_sync(FULLM, incl, d);
        if (lane >= d) incl += v;
    }
    if (lane == 31) s_wosum[wid] = incl;

    // ---- g/t warp reduce: off the scan path, still before barrier 1 ----
#pragma unroll
    for (int d = 16; d > 0; d >>= 1) {
        sg += __shfl_down_sync(FULLM, sg, d);
        st += __shfl_down_sync(FULLM, st, d);
    }
    if (lane == 0) { s_wg[wid] = sg; s_wt[wid] = st; }
    __syncthreads();                      // barrier 1

    // ---- cross-warp prefix + scatter onset counts ----
    int wpre = 0;
#pragma unroll
    for (int w = 0; w < 8; w++) wpre += (w < wid) ? s_wosum[w] : 0;
    const int excl = wpre + incl - osum;   // exclusive offset-prefix of this thread

    unsigned m = onm;
    if (tid == 0) m &= ~1u;                // reference masks onsets at idx==0
    while (m) {
        const int j = __ffs(m) - 1;
        m &= m - 1;
        const int seg = excl + __popc(offm & ((2u << j) - 1u));  // inclusive cumsum at l
        if (seg < NMAX) atomicAdd(&s_counts[seg], 1);
    }

    // ---- combine (barrier-1 data only): hidden under the scatter above ----
    int   n_notes = 0;
    float tg = 0.f, tt = 0.f;
#pragma unroll
    for (int w = 0; w < 8; w++) { n_notes += s_wosum[w]; tg += s_wg[w]; tt += s_wt[w]; }
    const float dd = (tg - tt) * (1.0f / LEN);

    __syncthreads();                      // barrier 2 (histogram complete)

    // ---- per-note loss, block reduce (threads 0-127 = one note each) ----
    float val = 0.f;
    if (tid < NMAX) {
        float c = -(float)s_counts[tid];
        if (tid == 0) c -= (float)(offm & 1u);   // tid0's chunk holds offsets[b,0]
        if (tid >= n_notes) c = 0.f;
        const float diff = fabsf(c * dd / (c + 1e-6f));
        val = fmaxf(diff - 0.5f, 0.f);
    }
#pragma unroll
    for (int d = 16; d > 0; d >>= 1) val += __shfl_down_sync(FULLM, val, d);
    if (lane == 0 && wid < 4) s_red[wid] = val;   // warps 0-3 hold tid<128
    __syncthreads();                      // barrier 3

    // ---- single packed atomic: count in high bits, fixed-point sum low ----
    if (tid == 0) {
        const float bs = (s_red[0] + s_red[1]) + (s_red[2] + s_red[3]);
        const unsigned long long q =
            (unsigned long long)__float2ll_rn(bs * FP_SCALE);
        const unsigned long long add = (1ULL << CNT_SHIFT) + q;
        const unsigned long long old = atomicAdd(&g_pack, add);
        if ((old >> CNT_SHIFT) == (unsigned long long)(BATCH - 1)) {
            const unsigned long long tot = (old + add) & VAL_MASK;
            out[0] = (float)((double)tot * (1.0 / (double)FP_SCALE)
                              * (1.0 / (NMAX * BATCH)));
            g_pack = 0ULL;   // all 64 adds landed (count==64): safe to rearm
        }
    }
}

extern "C" void kernel_launch(void* const* d_in, const int* in_sizes, int n_in,
                              void* d_out, int out_size)
{
    const float* gen_f0   = (const float*)d_in[0];
    const float* contours = (const float*)d_in[1];
    const int*   onsets   = (const int*)d_in[2];
    const int*   offsets  = (const int*)d_in[3];
    // d_in[4] = n_notes_max (compile-time NMAX=128 for this shape)

    pitch_fused_kernel<<<BATCH, T1>>>(gen_f0, contours, onsets, offsets, (float*)d_out);
}